// round 15
// baseline (speedup 1.0000x reference)
#include <cuda_runtime.h>
#include <math.h>

// ---------------------------------------------------------------------------
// Compile-time stiffness coefficients (exact cofactor inverse of the 6x6
// compliance matrix, which is block-diagonal: asymmetric 3x3 block + 0.075*I).
// ---------------------------------------------------------------------------
constexpr double K_a = 1.0 / 0.21;          // 1/Ep
constexpr double K_b = 0.4 / 0.21;          // vp/Ep
constexpr double K_c = 0.4;                 // vp  (the asymmetry in row 2)
constexpr double K_A11 = K_a * K_a - K_b * K_c;
constexpr double K_DET = K_a * K_A11
                       - K_b * (K_b * (K_a + K_c))
                       - K_b * (K_c * (K_a + K_b));
constexpr float CM0  = (float)(K_A11 / K_DET);
constexpr float CM1  = (float)((K_b * (K_a + K_c)) / K_DET);
constexpr float CM23 = (float)(((K_b + K_c) * (K_a + K_b)) / K_DET);
constexpr float CM4  = (float)((K_a * K_a - K_b * K_b) / K_DET);
constexpr float CSH  = (float)((0.21 / 2.8) * 0.25);                // 0.075*0.25

// Reduction state (zero at module load; the finalizing block restores zeros
// every call, so the kernel stays deterministic across graph replays).
__device__ double       g_sum  = 0.0;
__device__ unsigned int g_cnt  = 0u;
__device__ unsigned int g_done = 0u;

__global__ void __launch_bounds__(256)
biomech_loss_kernel(const float* __restrict__ gu,
                    const float* __restrict__ gv,
                    const float* __restrict__ gw,
                    const float* __restrict__ sd,
                    float* __restrict__ out,
                    int n)
{
    const int stride = gridDim.x * blockDim.x;
    float acc = 0.0f;
    int   cnt = 0;

    // Thread-per-point grid-stride loop with the sdf value prefetched one
    // iteration ahead, so gradient loads never wait on the current sdf load.
    // Gradient loads are issued ONLY for selected points (~50%): DRAM sector
    // traffic for gradients drops to ~58% of the full stream.
    int p = blockIdx.x * blockDim.x + threadIdx.x;
    float s_cur = (p < n) ? __ldcs(&sd[p]) : 1.0f;   // 1.0f => unselected

    for (; p < n; ) {
        const int pn = p + stride;
        float s_next = (pn < n) ? __ldcs(&sd[pn]) : 1.0f;

        if (s_cur < 1e-8f) {
            const float ux = __ldcs(&gu[3 * p + 0]);
            const float uy = __ldcs(&gu[3 * p + 1]);
            const float uz = __ldcs(&gu[3 * p + 2]);
            const float vx = __ldcs(&gv[3 * p + 0]);
            const float vy = __ldcs(&gv[3 * p + 1]);
            const float vz = __ldcs(&gv[3 * p + 2]);
            const float wx = __ldcs(&gw[3 * p + 0]);
            const float wy = __ldcs(&gw[3 * p + 1]);
            const float wz = __ldcs(&gw[3 * p + 2]);

            const float e0 = ux, e1 = vy, e2 = wz;
            const float s3 = uy + vx;
            const float s4 = uz + wx;
            const float s5 = wy + vz;
            const float q = CM0 * (e0 * e0 + e1 * e1)
                          + 2.0f * CM1 * (e0 * e1)
                          + CM23 * ((e0 + e1) * e2)
                          + CM4 * (e2 * e2)
                          + CSH * (s3 * s3 + s4 * s4 + s5 * s5);
            acc += q * q;
            cnt += 1;
        }

        p = pn;
        s_cur = s_next;
    }

    // Warp reduction.
    #pragma unroll
    for (int o = 16; o > 0; o >>= 1) {
        acc += __shfl_down_sync(0xFFFFFFFFu, acc, o);
        cnt += __shfl_down_sync(0xFFFFFFFFu, cnt, o);
    }

    __shared__ float sacc[8];
    __shared__ int   scnt[8];
    const int wid  = threadIdx.x >> 5;
    const int lane = threadIdx.x & 31;
    if (lane == 0) { sacc[wid] = acc; scnt[wid] = cnt; }
    __syncthreads();

    if (wid == 0) {
        acc = (lane < 8) ? sacc[lane] : 0.0f;
        cnt = (lane < 8) ? scnt[lane] : 0;
        #pragma unroll
        for (int o = 4; o > 0; o >>= 1) {
            acc += __shfl_down_sync(0xFFFFFFFFu, acc, o);
            cnt += __shfl_down_sync(0xFFFFFFFFu, cnt, o);
        }
        if (lane == 0) {
            atomicAdd(&g_sum, (double)acc);
            atomicAdd(&g_cnt, (unsigned int)cnt);
            __threadfence();
            unsigned int ticket = atomicAdd(&g_done, 1u);
            if (ticket == gridDim.x - 1u) {
                // Last block: all prior atomics visible (fence + atomic order).
                double       total = atomicAdd(&g_sum, 0.0);
                unsigned int c     = atomicAdd(&g_cnt, 0u);
                out[0] = (float)(sqrt(total) / (double)c);
                // Restore zero-state for the next (graph-replayed) call.
                g_sum  = 0.0;
                g_cnt  = 0u;
                g_done = 0u;
            }
        }
    }
}

extern "C" void kernel_launch(void* const* d_in, const int* in_sizes, int n_in,
                              void* d_out, int out_size)
{
    const float* gu = (const float*)d_in[0];
    const float* gv = (const float*)d_in[1];
    const float* gw = (const float*)d_in[2];
    const float* sd = (const float*)d_in[3];
    float* out = (float*)d_out;

    const int n = in_sizes[3];     // number of points

    int nsm = 152;
    if (cudaDeviceGetAttribute(&nsm, cudaDevAttrMultiProcessorCount, 0)
        != cudaSuccess || nsm <= 0) {
        nsm = 152;
    }

    // Prefer a thread count that divides n exactly (integral iterations per
    // thread); fall back to a plain persistent shape otherwise.
    int blocks = 0;
    const int cand[] = {768, 512, 384, 256, 128};
    for (int c : cand) {
        long thr = (long)c * 256;
        if (c <= 6 * nsm && n >= thr && n % thr == 0) { blocks = c; break; }
    }
    if (blocks == 0) {
        blocks = 6 * nsm;
        int max_needed = (n + 255) / 256;
        if (blocks > max_needed) blocks = max_needed;
        if (blocks < 1) blocks = 1;
    }

    biomech_loss_kernel<<<blocks, 256>>>(gu, gv, gw, sd, out, n);
}